// round 4
// baseline (speedup 1.0000x reference)
#include <cuda_runtime.h>

#define IN_DIM   2048
#define OUT_DIM  14951
#define THREADS  256
#define EPS      1e-12f

__global__ __launch_bounds__(THREADS)
void hc_kernel(const float* __restrict__ x,
               const float* __restrict__ scale,
               const float* __restrict__ bias,
               float* __restrict__ out)
{
    __shared__ float xch[IN_DIM];          // 8 KB transpose buffer
    __shared__ float sred[THREADS / 32];
    __shared__ float sc;

    const int t    = threadIdx.x;
    const int row  = blockIdx.x;
    const int lane = t & 31;

    // res[q] holds element n = q*256 + t
    float res[8];

    const float* __restrict__ xr = x + (size_t)row * IN_DIM;

    // ---- load (coalesced) + sum of squares ----
    float ss = 0.f;
#pragma unroll
    for (int q = 0; q < 8; ++q) {
        float v = xr[q * THREADS + t];
        res[q] = v;
        ss += v * v;
    }
#pragma unroll
    for (int o = 16; o; o >>= 1) ss += __shfl_xor_sync(0xFFFFFFFFu, ss, o);
    if (lane == 0) sred[t >> 5] = ss;
    __syncthreads();
    if (t == 0) {
        float tot = 0.f;
#pragma unroll
        for (int w = 0; w < THREADS / 32; ++w) tot += sred[w];
        sc = -scale[0] * rsqrtf(fmaxf(tot, EPS));
    }

    // ---- 3 register stages (bits 8..10 of n == bits of q) ----
#pragma unroll
    for (int B = 1; B < 8; B <<= 1) {
#pragma unroll
        for (int q = 0; q < 8; ++q) {
            if (!(q & B)) {
                float a0 = res[q], a1 = res[q | B];
                res[q]     = a0 + a1;
                res[q | B] = a0 - a1;
            }
        }
    }

    // ---- 5 shuffle stages (bits 0..4 of n == lane bits of t) ----
#pragma unroll
    for (int h = 1; h <= 16; h <<= 1) {
#pragma unroll
        for (int q = 0; q < 8; ++q) {
            float o = __shfl_xor_sync(0xFFFFFFFFu, res[q], h);
            res[q] = (t & h) ? (o - res[q]) : (res[q] + o);
        }
    }

    // ---- single transpose round-trip: warp-bits (5..7 of n) -> register index u ----
#pragma unroll
    for (int q = 0; q < 8; ++q) xch[q * THREADS + t] = res[q];
    __syncthreads();

    const int Q = t >> 5;               // fixed q-coordinate for this thread
#pragma unroll
    for (int u = 0; u < 8; ++u) res[u] = xch[Q * THREADS + u * 32 + lane];

    // ---- 3 register stages over u (bits 5..7 of n) ----
#pragma unroll
    for (int B = 1; B < 8; B <<= 1) {
#pragma unroll
        for (int u = 0; u < 8; ++u) {
            if (!(u & B)) {
                float a0 = res[u], a1 = res[u | B];
                res[u]     = a0 + a1;
                res[u | B] = a0 - a1;
            }
        }
    }
    // now res[u] = y[Q*256 + u*32 + lane]

    const float c = sc;                 // visible: written before the __syncthreads above
    float* __restrict__ orow = out + (size_t)row * OUT_DIM;
    const int base0 = Q * THREADS + lane;

    // ---- epilogue: out[row, j] = c * y[j & 2047] + bias[j]
    // j = base0 + u*32 + 2048*k  =>  y[j & 2047] = res[u]   (register-resident)
#pragma unroll
    for (int k = 0; k < 7; ++k) {
#pragma unroll
        for (int u = 0; u < 8; ++u) {
            int j = base0 + u * 32 + k * IN_DIM;
            orow[j] = fmaf(c, res[u], __ldg(bias + j));
        }
    }
    // k = 7 (partial: j < 14951)
#pragma unroll
    for (int u = 0; u < 8; ++u) {
        int j = base0 + u * 32 + 7 * IN_DIM;
        if (j < OUT_DIM) orow[j] = fmaf(c, res[u], __ldg(bias + j));
    }
}

extern "C" void kernel_launch(void* const* d_in, const int* in_sizes, int n_in,
                              void* d_out, int out_size)
{
    const float* x     = (const float*)d_in[0];
    const float* scale = (const float*)d_in[1];
    const float* bias  = (const float*)d_in[2];
    float* out = (float*)d_out;

    const int batch = in_sizes[0] / IN_DIM;     // 4096
    hc_kernel<<<batch, THREADS>>>(x, scale, bias, out);
}